// round 2
// baseline (speedup 1.0000x reference)
#include <cuda_runtime.h>

#define H 128
#define HH (H * H)
#define TILE_N 64
#define NT 256
#define MAXN 50176

// Scratch (device globals — no allocation allowed)
__device__ float g_h0[(size_t)MAXN * H];
__device__ float g_agg[(size_t)MAXN * H];
__device__ float g_x1[(size_t)MAXN * H];
__device__ float g_deg[MAXN];
__device__ float g_wt[5 * HH];   // transposed weights: [k][j]

// ---------------------------------------------------------------------------
// Transpose W[j][k] (row-major [H,H]) into g_wt slot as Wt[k][j]
// ---------------------------------------------------------------------------
__global__ void transpose_w(const float* __restrict__ W, int slot) {
    int idx = blockIdx.x * blockDim.x + threadIdx.x;
    if (idx < HH) {
        int j = idx >> 7;
        int k = idx & 127;
        g_wt[slot * HH + k * H + j] = W[idx];
    }
}

// ---------------------------------------------------------------------------
// Zero agg (+ deg on request)
// ---------------------------------------------------------------------------
__global__ void zero_kernel(int N, int zero_deg) {
    int idx = blockIdx.x * blockDim.x + threadIdx.x;
    int total4 = N * (H / 4);
    if (idx < total4) ((float4*)g_agg)[idx] = make_float4(0.f, 0.f, 0.f, 0.f);
    if (zero_deg && idx < N) g_deg[idx] = 0.f;
}

// ---------------------------------------------------------------------------
// Degree: deg[tgt] += 1 per edge (edge_index is int32: [2, E] row-major)
// ---------------------------------------------------------------------------
__global__ void deg_kernel(const int* __restrict__ ei, int E) {
    int e = blockIdx.x * blockDim.x + threadIdx.x;
    if (e < E) atomicAdd(&g_deg[ei[E + e]], 1.0f);
}

// ---------------------------------------------------------------------------
// Scatter: agg[tgt] += h[src]; one warp per edge, float4 per lane,
// vector reduction red.global.add.v4.f32 (sm_90+)
// ---------------------------------------------------------------------------
__global__ void scatter_kernel(int xsel, const int* __restrict__ ei, int E) {
    int gt = blockIdx.x * blockDim.x + threadIdx.x;
    int e = gt >> 5;
    if (e >= E) return;
    int lane = gt & 31;
    const float* h = xsel ? g_x1 : g_h0;
    int s = ei[e];
    int t = ei[E + e];
    float4 v = *(const float4*)(h + (size_t)s * H + lane * 4);
    float* dst = g_agg + (size_t)t * H + lane * 4;
    asm volatile("red.global.add.v4.f32 [%0], {%1,%2,%3,%4};"
                 :: "l"(dst), "f"(v.x), "f"(v.y), "f"(v.z), "f"(v.w)
                 : "memory");
}

// ---------------------------------------------------------------------------
// Core register-tiled accumulate: 4 nodes x 8 outputs per thread.
// Ws is [k][j] in smem; thread's outputs are j = jlo..jlo+3 and jlo+64..jlo+67.
// ---------------------------------------------------------------------------
__device__ __forceinline__ void mm_accum(const float* __restrict__ Xs,
                                         const float* __restrict__ Ws,
                                         int n0, int jlo, float acc[4][8]) {
#pragma unroll 4
    for (int k = 0; k < H; k++) {
        float4 wa = *(const float4*)(Ws + k * H + jlo);
        float4 wb = *(const float4*)(Ws + k * H + jlo + 64);
#pragma unroll
        for (int i = 0; i < 4; i++) {
            float x = Xs[(n0 + i) * H + k];
            acc[i][0] = fmaf(x, wa.x, acc[i][0]);
            acc[i][1] = fmaf(x, wa.y, acc[i][1]);
            acc[i][2] = fmaf(x, wa.z, acc[i][2]);
            acc[i][3] = fmaf(x, wa.w, acc[i][3]);
            acc[i][4] = fmaf(x, wb.x, acc[i][4]);
            acc[i][5] = fmaf(x, wb.y, acc[i][5]);
            acc[i][6] = fmaf(x, wb.z, acc[i][6]);
            acc[i][7] = fmaf(x, wb.w, acc[i][7]);
        }
    }
}

// ---------------------------------------------------------------------------
// Input layer: h0 = relu( concat(attr,cc,bl,exist) @ W_in^T + b_in )
// ---------------------------------------------------------------------------
__global__ void input_gemm(const float* __restrict__ attr, int ATTR,
                           const float* __restrict__ cc,
                           const float* __restrict__ bl,
                           const float* __restrict__ exist,
                           const float* __restrict__ b, int N) {
    extern __shared__ float sm[];
    float* Xs = sm;              // TILE_N * H
    float* Ws = sm + TILE_N * H; // HH
    const int tid = threadIdx.x;
    const int nb = blockIdx.x * TILE_N;

    for (int idx = tid; idx < HH; idx += NT) Ws[idx] = g_wt[idx]; // slot 0

    for (int idx = tid; idx < TILE_N * H; idx += NT) {
        int n = idx >> 7, k = idx & 127;
        int gn = nb + n;
        float v = 0.f;
        if (gn < N) {
            if (k < ATTR)            v = attr[(size_t)gn * ATTR + k];
            else if (k == ATTR)      v = cc[gn];
            else if (k == ATTR + 1)  v = bl[gn];
            else if (k == ATTR + 2)  v = exist[gn];
        }
        Xs[idx] = v;
    }
    __syncthreads();

    const int jt = tid & 15, nt = tid >> 4;
    const int jlo = jt * 4, n0 = nt * 4;
    float acc[4][8] = {};
    mm_accum(Xs, Ws, n0, jlo, acc);

#pragma unroll
    for (int i = 0; i < 4; i++) {
        int gn = nb + n0 + i;
        if (gn >= N) continue;
        float4 o1, o2;
        o1.x = fmaxf(acc[i][0] + b[jlo + 0], 0.f);
        o1.y = fmaxf(acc[i][1] + b[jlo + 1], 0.f);
        o1.z = fmaxf(acc[i][2] + b[jlo + 2], 0.f);
        o1.w = fmaxf(acc[i][3] + b[jlo + 3], 0.f);
        o2.x = fmaxf(acc[i][4] + b[jlo + 64], 0.f);
        o2.y = fmaxf(acc[i][5] + b[jlo + 65], 0.f);
        o2.z = fmaxf(acc[i][6] + b[jlo + 66], 0.f);
        o2.w = fmaxf(acc[i][7] + b[jlo + 67], 0.f);
        *(float4*)(g_h0 + (size_t)gn * H + jlo) = o1;
        *(float4*)(g_h0 + (size_t)gn * H + jlo + 64) = o2;
    }
}

// ---------------------------------------------------------------------------
// SAGE layer: out = post( X@Ws^T + bs + (agg/max(deg,1))@Wn^T + bn )
// xsel: 0 -> X = g_h0, 1 -> X = g_x1
// out: nullptr -> write g_x1 (layer 1), else write out (layer 2)
// do_relu: relu before exist multiply (layer 1 only)
// ---------------------------------------------------------------------------
__global__ void sage_gemm(int xsel, int wslot_self, int wslot_neigh,
                          const float* __restrict__ bs,
                          const float* __restrict__ bn,
                          const float* __restrict__ exist,
                          float* out, int N, int do_relu) {
    extern __shared__ float sm[];
    float* Xs = sm;
    float* Ws = sm + TILE_N * H;
    const int tid = threadIdx.x;
    const int nb = blockIdx.x * TILE_N;
    const int jt = tid & 15, nt = tid >> 4;
    const int jlo = jt * 4, n0 = nt * 4;
    const float* Xself = xsel ? g_x1 : g_h0;
    float* dst = out ? out : g_x1;

    float acc[4][8] = {};

    // phase 1: self term
    for (int idx = tid; idx < HH; idx += NT) Ws[idx] = g_wt[wslot_self * HH + idx];
    for (int idx = tid; idx < TILE_N * (H / 4); idx += NT) {
        int n = idx >> 5, kq = idx & 31;
        int gn = nb + n;
        float4 v = make_float4(0.f, 0.f, 0.f, 0.f);
        if (gn < N) v = *(const float4*)(Xself + (size_t)gn * H + kq * 4);
        *(float4*)(Xs + n * H + kq * 4) = v;
    }
    __syncthreads();
    mm_accum(Xs, Ws, n0, jlo, acc);
    __syncthreads();

    // phase 2: neighbor-mean term
    for (int idx = tid; idx < HH; idx += NT) Ws[idx] = g_wt[wslot_neigh * HH + idx];
    for (int idx = tid; idx < TILE_N * (H / 4); idx += NT) {
        int n = idx >> 5, kq = idx & 31;
        int gn = nb + n;
        float4 v = make_float4(0.f, 0.f, 0.f, 0.f);
        if (gn < N) {
            float inv = 1.0f / fmaxf(g_deg[gn], 1.0f);
            float4 a = *(const float4*)(g_agg + (size_t)gn * H + kq * 4);
            v = make_float4(a.x * inv, a.y * inv, a.z * inv, a.w * inv);
        }
        *(float4*)(Xs + n * H + kq * 4) = v;
    }
    __syncthreads();
    mm_accum(Xs, Ws, n0, jlo, acc);

#pragma unroll
    for (int i = 0; i < 4; i++) {
        int gn = nb + n0 + i;
        if (gn >= N) continue;
        float ex = exist[gn];
        float o[8];
#pragma unroll
        for (int r = 0; r < 4; r++) {
            float v1 = acc[i][r] + bs[jlo + r] + bn[jlo + r];
            float v2 = acc[i][r + 4] + bs[jlo + 64 + r] + bn[jlo + 64 + r];
            if (do_relu) { v1 = fmaxf(v1, 0.f); v2 = fmaxf(v2, 0.f); }
            o[r] = v1 * ex;
            o[r + 4] = v2 * ex;
        }
        *(float4*)(dst + (size_t)gn * H + jlo) = make_float4(o[0], o[1], o[2], o[3]);
        *(float4*)(dst + (size_t)gn * H + jlo + 64) = make_float4(o[4], o[5], o[6], o[7]);
    }
}

// ---------------------------------------------------------------------------
extern "C" void kernel_launch(void* const* d_in, const int* in_sizes, int n_in,
                              void* d_out, int out_size) {
    const float* attr  = (const float*)d_in[0];
    const float* cc    = (const float*)d_in[1];
    const float* bl    = (const float*)d_in[2];
    const float* exist = (const float*)d_in[3];
    const float* W_in  = (const float*)d_in[4];
    const float* b_in  = (const float*)d_in[5];
    const float* W1s   = (const float*)d_in[6];
    const float* b1s   = (const float*)d_in[7];
    const float* W1n   = (const float*)d_in[8];
    const float* b1n   = (const float*)d_in[9];
    const float* W2s   = (const float*)d_in[10];
    const float* b2s   = (const float*)d_in[11];
    const float* W2n   = (const float*)d_in[12];
    const float* b2n   = (const float*)d_in[13];
    const int*   ei    = (const int*)d_in[14];   // int32 (JAX x64 disabled)

    const int N    = in_sizes[3];
    const int ATTR = in_sizes[0] / N;
    const int E    = in_sizes[14] / 2;
    float* out = (float*)d_out;

    const int SMEM = (TILE_N * H + HH) * (int)sizeof(float);
    cudaFuncSetAttribute(input_gemm, cudaFuncAttributeMaxDynamicSharedMemorySize, SMEM);
    cudaFuncSetAttribute(sage_gemm,  cudaFuncAttributeMaxDynamicSharedMemorySize, SMEM);

    const int gemm_grid = (N + TILE_N - 1) / TILE_N;
    const int zero_grid = (N * (H / 4) + NT - 1) / NT;
    const int deg_grid  = (E + NT - 1) / NT;
    const long long sc_threads = (long long)E * 32;
    const int sc_grid = (int)((sc_threads + NT - 1) / NT);

    // weight transposes (slots: 0=W_in, 1=W1s, 2=W1n, 3=W2s, 4=W2n)
    transpose_w<<<(HH + NT - 1) / NT, NT>>>(W_in, 0);
    transpose_w<<<(HH + NT - 1) / NT, NT>>>(W1s, 1);
    transpose_w<<<(HH + NT - 1) / NT, NT>>>(W1n, 2);
    transpose_w<<<(HH + NT - 1) / NT, NT>>>(W2s, 3);
    transpose_w<<<(HH + NT - 1) / NT, NT>>>(W2n, 4);

    // zero agg + deg
    zero_kernel<<<zero_grid, NT>>>(N, 1);

    // input layer
    input_gemm<<<gemm_grid, NT, SMEM>>>(attr, ATTR, cc, bl, exist, b_in, N);

    // degree (shared by both layers)
    deg_kernel<<<deg_grid, NT>>>(ei, E);

    // layer 1
    scatter_kernel<<<sc_grid, NT>>>(0, ei, E);
    sage_gemm<<<gemm_grid, NT, SMEM>>>(0, 1, 2, b1s, b1n, exist, nullptr, N, 1);

    // layer 2
    zero_kernel<<<zero_grid, NT>>>(N, 0);
    scatter_kernel<<<sc_grid, NT>>>(1, ei, E);
    sage_gemm<<<gemm_grid, NT, SMEM>>>(1, 3, 4, b2s, b2n, exist, out, N, 0);
}

// round 3
// speedup vs baseline: 1.0624x; 1.0624x over previous
#include <cuda_runtime.h>

#define H 128
#define HH (H * H)
#define TILE_N 64
#define NT 256
#define MAXN 50176

typedef unsigned long long ull;

// Scratch (device globals — no allocation allowed)
__device__ float g_h0[(size_t)MAXN * H];
__device__ float g_agg[(size_t)MAXN * H];
__device__ float g_x1[(size_t)MAXN * H];
__device__ float g_deg[MAXN];
__device__ float g_wt[5 * HH];   // transposed weights: [k][j]

// ---------------------------------------------------------------------------
// f32x2 helpers (FFMA2 path — packed fp32 pairs, 2 FMAs per fma-pipe slot)
// ---------------------------------------------------------------------------
__device__ __forceinline__ ull splat2(float x) {
    ull d;
    asm("mov.b64 %0, {%1, %1};" : "=l"(d) : "f"(x));
    return d;
}
__device__ __forceinline__ void fma2(ull& acc, ull a, ull b) {
    asm("fma.rn.f32x2 %0, %1, %2, %0;" : "+l"(acc) : "l"(a), "l"(b));
}
__device__ __forceinline__ void unpack2(ull v, float& lo, float& hi) {
    asm("mov.b64 {%0, %1}, %2;" : "=f"(lo), "=f"(hi) : "l"(v));
}

// ---------------------------------------------------------------------------
// Transpose all five W[j][k] ([H,H] row-major) into g_wt slots as Wt[k][j].
// gridDim.y = slot.
// ---------------------------------------------------------------------------
__global__ void transpose_w_all(const float* __restrict__ W0,
                                const float* __restrict__ W1,
                                const float* __restrict__ W2,
                                const float* __restrict__ W3,
                                const float* __restrict__ W4) {
    int slot = blockIdx.y;
    const float* W = (slot == 0) ? W0 : (slot == 1) ? W1 : (slot == 2) ? W2
                   : (slot == 3) ? W3 : W4;
    int idx = blockIdx.x * blockDim.x + threadIdx.x;
    if (idx < HH) {
        int j = idx >> 7;
        int k = idx & 127;
        g_wt[slot * HH + k * H + j] = W[idx];
    }
}

// ---------------------------------------------------------------------------
// Zero agg (+ deg on request)
// ---------------------------------------------------------------------------
__global__ void zero_kernel(int N, int zero_deg) {
    int idx = blockIdx.x * blockDim.x + threadIdx.x;
    int total4 = N * (H / 4);
    if (idx < total4) ((float4*)g_agg)[idx] = make_float4(0.f, 0.f, 0.f, 0.f);
    if (zero_deg && idx < N) g_deg[idx] = 0.f;
}

// ---------------------------------------------------------------------------
// Scatter: agg[tgt] += h[src]; one warp per edge, float4 per lane,
// vector reduction red.global.add.v4.f32. Layer-1 variant (do_deg=1) also
// accumulates deg[tgt] from lane 0.
// ---------------------------------------------------------------------------
__global__ void scatter_kernel(int xsel, const int* __restrict__ ei, int E,
                               int do_deg) {
    int gt = blockIdx.x * blockDim.x + threadIdx.x;
    int e = gt >> 5;
    if (e >= E) return;
    int lane = gt & 31;
    const float* h = xsel ? g_x1 : g_h0;
    int s = ei[e];
    int t = ei[E + e];
    if (do_deg && lane == 0)
        asm volatile("red.global.add.f32 [%0], %1;" :: "l"(&g_deg[t]), "f"(1.0f) : "memory");
    float4 v = *(const float4*)(h + (size_t)s * H + lane * 4);
    float* dst = g_agg + (size_t)t * H + lane * 4;
    asm volatile("red.global.add.v4.f32 [%0], {%1,%2,%3,%4};"
                 :: "l"(dst), "f"(v.x), "f"(v.y), "f"(v.z), "f"(v.w)
                 : "memory");
}

// ---------------------------------------------------------------------------
// Register-tiled accumulate with FFMA2: 4 nodes x 8 outputs per thread,
// accumulators packed over j (4 f32x2 per node). Weights packed for free
// (ulonglong2 loads of Wt rows); x splatted once per (k, node).
// ---------------------------------------------------------------------------
__device__ __forceinline__ void mm_accum(const float* __restrict__ Xs,
                                         const float* __restrict__ Ws,
                                         int n0, int jlo, ull acc[4][4]) {
#pragma unroll
    for (int k4 = 0; k4 < H; k4 += 4) {
        float4 xv[4];
#pragma unroll
        for (int i = 0; i < 4; i++)
            xv[i] = *(const float4*)(Xs + (n0 + i) * H + k4);
#pragma unroll
        for (int kk = 0; kk < 4; kk++) {
            const int k = k4 + kk;
            ulonglong2 wa = *(const ulonglong2*)(Ws + k * H + jlo);
            ulonglong2 wb = *(const ulonglong2*)(Ws + k * H + jlo + 64);
#pragma unroll
            for (int i = 0; i < 4; i++) {
                float xs = (kk == 0) ? xv[i].x : (kk == 1) ? xv[i].y
                         : (kk == 2) ? xv[i].z : xv[i].w;
                ull x2 = splat2(xs);
                fma2(acc[i][0], x2, wa.x);
                fma2(acc[i][1], x2, wa.y);
                fma2(acc[i][2], x2, wb.x);
                fma2(acc[i][3], x2, wb.y);
            }
        }
    }
}

// ---------------------------------------------------------------------------
// Input layer: h0 = relu( concat(attr,cc,bl,exist) @ W_in^T + b_in )
// ---------------------------------------------------------------------------
__global__ void input_gemm(const float* __restrict__ attr, int ATTR,
                           const float* __restrict__ cc,
                           const float* __restrict__ bl,
                           const float* __restrict__ exist,
                           const float* __restrict__ b, int N) {
    extern __shared__ float sm[];
    float* Xs = sm;              // TILE_N * H
    float* Ws = sm + TILE_N * H; // HH
    const int tid = threadIdx.x;
    const int nb = blockIdx.x * TILE_N;

    for (int idx = tid; idx < HH; idx += NT) Ws[idx] = g_wt[idx]; // slot 0

    for (int idx = tid; idx < TILE_N * H; idx += NT) {
        int n = idx >> 7, k = idx & 127;
        int gn = nb + n;
        float v = 0.f;
        if (gn < N) {
            if (k < ATTR)            v = attr[(size_t)gn * ATTR + k];
            else if (k == ATTR)      v = cc[gn];
            else if (k == ATTR + 1)  v = bl[gn];
            else if (k == ATTR + 2)  v = exist[gn];
        }
        Xs[idx] = v;
    }
    __syncthreads();

    const int jt = tid & 15, nt = tid >> 4;
    const int jlo = jt * 4, n0 = nt * 4;
    ull acc[4][4] = {};
    mm_accum(Xs, Ws, n0, jlo, acc);

#pragma unroll
    for (int i = 0; i < 4; i++) {
        int gn = nb + n0 + i;
        if (gn >= N) continue;
        float o[8];
        unpack2(acc[i][0], o[0], o[1]);
        unpack2(acc[i][1], o[2], o[3]);
        unpack2(acc[i][2], o[4], o[5]);
        unpack2(acc[i][3], o[6], o[7]);
        float4 o1, o2;
        o1.x = fmaxf(o[0] + b[jlo + 0], 0.f);
        o1.y = fmaxf(o[1] + b[jlo + 1], 0.f);
        o1.z = fmaxf(o[2] + b[jlo + 2], 0.f);
        o1.w = fmaxf(o[3] + b[jlo + 3], 0.f);
        o2.x = fmaxf(o[4] + b[jlo + 64], 0.f);
        o2.y = fmaxf(o[5] + b[jlo + 65], 0.f);
        o2.z = fmaxf(o[6] + b[jlo + 66], 0.f);
        o2.w = fmaxf(o[7] + b[jlo + 67], 0.f);
        *(float4*)(g_h0 + (size_t)gn * H + jlo) = o1;
        *(float4*)(g_h0 + (size_t)gn * H + jlo + 64) = o2;
    }
}

// ---------------------------------------------------------------------------
// SAGE layer: out = post( X@Ws^T + bs + (agg/max(deg,1))@Wn^T + bn )
// xsel: 0 -> X = g_h0, 1 -> X = g_x1
// out: nullptr -> write g_x1 (layer 1), else write out (layer 2)
// do_relu: relu before exist multiply (layer 1 only)
// ---------------------------------------------------------------------------
__global__ void sage_gemm(int xsel, int wslot_self, int wslot_neigh,
                          const float* __restrict__ bs,
                          const float* __restrict__ bn,
                          const float* __restrict__ exist,
                          float* out, int N, int do_relu) {
    extern __shared__ float sm[];
    float* Xs = sm;
    float* Ws = sm + TILE_N * H;
    const int tid = threadIdx.x;
    const int nb = blockIdx.x * TILE_N;
    const int jt = tid & 15, nt = tid >> 4;
    const int jlo = jt * 4, n0 = nt * 4;
    const float* Xself = xsel ? g_x1 : g_h0;
    float* dst = out ? out : g_x1;

    ull acc[4][4] = {};

    // phase 1: self term
    for (int idx = tid; idx < HH; idx += NT) Ws[idx] = g_wt[wslot_self * HH + idx];
    for (int idx = tid; idx < TILE_N * (H / 4); idx += NT) {
        int n = idx >> 5, kq = idx & 31;
        int gn = nb + n;
        float4 v = make_float4(0.f, 0.f, 0.f, 0.f);
        if (gn < N) v = *(const float4*)(Xself + (size_t)gn * H + kq * 4);
        *(float4*)(Xs + n * H + kq * 4) = v;
    }
    __syncthreads();
    mm_accum(Xs, Ws, n0, jlo, acc);
    __syncthreads();

    // phase 2: neighbor-mean term
    for (int idx = tid; idx < HH; idx += NT) Ws[idx] = g_wt[wslot_neigh * HH + idx];
    for (int idx = tid; idx < TILE_N * (H / 4); idx += NT) {
        int n = idx >> 5, kq = idx & 31;
        int gn = nb + n;
        float4 v = make_float4(0.f, 0.f, 0.f, 0.f);
        if (gn < N) {
            float inv = 1.0f / fmaxf(g_deg[gn], 1.0f);
            float4 a = *(const float4*)(g_agg + (size_t)gn * H + kq * 4);
            v = make_float4(a.x * inv, a.y * inv, a.z * inv, a.w * inv);
        }
        *(float4*)(Xs + n * H + kq * 4) = v;
    }
    __syncthreads();
    mm_accum(Xs, Ws, n0, jlo, acc);

#pragma unroll
    for (int i = 0; i < 4; i++) {
        int gn = nb + n0 + i;
        if (gn >= N) continue;
        float ex = exist[gn];
        float o[8];
        unpack2(acc[i][0], o[0], o[1]);
        unpack2(acc[i][1], o[2], o[3]);
        unpack2(acc[i][2], o[4], o[5]);
        unpack2(acc[i][3], o[6], o[7]);
        float r[8];
#pragma unroll
        for (int q = 0; q < 4; q++) {
            float v1 = o[q] + bs[jlo + q] + bn[jlo + q];
            float v2 = o[q + 4] + bs[jlo + 64 + q] + bn[jlo + 64 + q];
            if (do_relu) { v1 = fmaxf(v1, 0.f); v2 = fmaxf(v2, 0.f); }
            r[q] = v1 * ex;
            r[q + 4] = v2 * ex;
        }
        *(float4*)(dst + (size_t)gn * H + jlo) = make_float4(r[0], r[1], r[2], r[3]);
        *(float4*)(dst + (size_t)gn * H + jlo + 64) = make_float4(r[4], r[5], r[6], r[7]);
    }
}

// ---------------------------------------------------------------------------
extern "C" void kernel_launch(void* const* d_in, const int* in_sizes, int n_in,
                              void* d_out, int out_size) {
    const float* attr  = (const float*)d_in[0];
    const float* cc    = (const float*)d_in[1];
    const float* bl    = (const float*)d_in[2];
    const float* exist = (const float*)d_in[3];
    const float* W_in  = (const float*)d_in[4];
    const float* b_in  = (const float*)d_in[5];
    const float* W1s   = (const float*)d_in[6];
    const float* b1s   = (const float*)d_in[7];
    const float* W1n   = (const float*)d_in[8];
    const float* b1n   = (const float*)d_in[9];
    const float* W2s   = (const float*)d_in[10];
    const float* b2s   = (const float*)d_in[11];
    const float* W2n   = (const float*)d_in[12];
    const float* b2n   = (const float*)d_in[13];
    const int*   ei    = (const int*)d_in[14];   // int32 (JAX x64 disabled)

    const int N    = in_sizes[3];
    const int ATTR = in_sizes[0] / N;
    const int E    = in_sizes[14] / 2;
    float* out = (float*)d_out;

    const int SMEM = (TILE_N * H + HH) * (int)sizeof(float);
    cudaFuncSetAttribute(input_gemm, cudaFuncAttributeMaxDynamicSharedMemorySize, SMEM);
    cudaFuncSetAttribute(sage_gemm,  cudaFuncAttributeMaxDynamicSharedMemorySize, SMEM);

    const int gemm_grid = (N + TILE_N - 1) / TILE_N;
    const int zero_grid = (N * (H / 4) + NT - 1) / NT;
    const long long sc_threads = (long long)E * 32;
    const int sc_grid = (int)((sc_threads + NT - 1) / NT);

    // weight transposes (slots: 0=W_in, 1=W1s, 2=W1n, 3=W2s, 4=W2n) — one launch
    dim3 tr_grid((HH + NT - 1) / NT, 5);
    transpose_w_all<<<tr_grid, NT>>>(W_in, W1s, W1n, W2s, W2n);

    // zero agg + deg
    zero_kernel<<<zero_grid, NT>>>(N, 1);

    // input layer
    input_gemm<<<gemm_grid, NT, SMEM>>>(attr, ATTR, cc, bl, exist, b_in, N);

    // layer 1 (scatter also accumulates degree, reused by layer 2)
    scatter_kernel<<<sc_grid, NT>>>(0, ei, E, 1);
    sage_gemm<<<gemm_grid, NT, SMEM>>>(0, 1, 2, b1s, b1n, exist, nullptr, N, 1);

    // layer 2
    zero_kernel<<<zero_grid, NT>>>(N, 0);
    scatter_kernel<<<sc_grid, NT>>>(1, ei, E, 0);
    sage_gemm<<<gemm_grid, NT, SMEM>>>(1, 3, 4, b2s, b2n, exist, out, N, 0);
}